// round 4
// baseline (speedup 1.0000x reference)
#include <cuda_runtime.h>
#include <math.h>
#include <limits.h>

// CRF loss: out[b] = logZ(b) - label_score(b).  B=512, S=512, L=128.
//
// Scaled linear-space forward recursion. One block of 512 threads per batch:
// (j in [0,128)) x (q in [0,4)). Thread (j,q) owns rows [32q,32q+32) of
// column j of E=exp(trans) as 16 f32x2 regs (32 regs -> 8 warps/SMSP).
// Per step: partial s via packed fma.rn.f32x2, quarters combined with two
// shfl_xor, U' = s * rcp(U_0) * exp(x_t) (exp/rcp/log all off the
// inter-thread critical path), U double-buffered in skewed shared
// (4-float pad per 32 -> conflict-free 4-address broadcast LDS.128),
// ONE __syncthreads per step. Blocks scheduled longest-first via a
// bitonic-sorted permutation (tail balance for 1.7 waves).

#define LDIM 128

__device__ int d_perm[1024];

__device__ __forceinline__ unsigned long long pack_f32x2(float lo, float hi) {
    unsigned long long r;
    asm("mov.b64 %0, {%1, %2};" : "=l"(r) : "f"(lo), "f"(hi));
    return r;
}
__device__ __forceinline__ void unpack_f32x2(unsigned long long v, float& lo, float& hi) {
    asm("mov.b64 {%0, %1}, %2;" : "=f"(lo), "=f"(hi) : "l"(v));
}
__device__ __forceinline__ unsigned long long fma_f32x2(unsigned long long a,
                                                        unsigned long long b,
                                                        unsigned long long c) {
    unsigned long long d;
    asm("fma.rn.f32x2 %0, %1, %2, %3;" : "=l"(d) : "l"(a), "l"(b), "l"(c));
    return d;
}
__device__ __forceinline__ unsigned long long add_f32x2(unsigned long long a,
                                                        unsigned long long b) {
    unsigned long long d;
    asm("add.rn.f32x2 %0, %1, %2;" : "=l"(d) : "l"(a), "l"(b));
    return d;
}
__device__ __forceinline__ float rcp_approx(float x) {
    float r;
    asm("rcp.approx.ftz.f32 %0, %1;" : "=f"(r) : "f"(x));
    return r;
}

// ---------------- longest-first permutation (bitonic, 1 block) ------------
__global__ void sort_len_kernel(const int* __restrict__ length, int B, int S)
{
    __shared__ int key[1024];
    __shared__ int val[1024];
    const int t = threadIdx.x;

    int k = INT_MAX;          // pads sort to the end
    if (t < B) {
        int L = length[t];
        L = L < 1 ? 1 : (L > S ? S : L);
        k = -L;               // ascending sort on -len => longest first
    }
    key[t] = k;
    val[t] = t;
    __syncthreads();

    for (int kk = 2; kk <= 1024; kk <<= 1) {
        for (int s = kk >> 1; s > 0; s >>= 1) {
            int p = t ^ s;
            if (p > t) {
                bool up = ((t & kk) == 0);
                int kt = key[t], kp = key[p];
                if ((kt > kp) == up) {
                    key[t] = kp; key[p] = kt;
                    int vt = val[t]; val[t] = val[p]; val[p] = vt;
                }
            }
            __syncthreads();
        }
    }
    if (t < B) d_perm[t] = val[t];
}

// ---------------- main CRF kernel -----------------------------------------
__global__ __launch_bounds__(512, 2)
void crf_forward_kernel(const float* __restrict__ input,
                        const int*   __restrict__ label,
                        const int*   __restrict__ length,
                        const float* __restrict__ trans,
                        float* __restrict__ out,
                        int S)
{
    // skewed U layout: U[i] stored at float index i + 4*(i>>5); 136 = 16B mult
    __shared__ __align__(16) float u_sh[2][136];
    __shared__ float wred[16];
    __shared__ float s_x00;
    __shared__ float s_labelscore;

    const int tid  = threadIdx.x;
    const int w    = tid >> 5;          // warp 0..15
    const int l    = tid & 31;
    const int q    = l >> 3;            // quarter 0..3 (i-split)
    const int jlo  = l & 7;
    const int j    = w * 8 + jlo;       // column 0..127
    const int b    = d_perm[blockIdx.x];

    int len = length[b];
    len = len < 1 ? 1 : (len > S ? S : len);

    const float* xb   = input + (size_t)b * S * LDIM;
    const int*   labb = label + (size_t)b * S;

    // ---------------- label score (point + transition) ----------------
    float ls = 0.f;
    for (int t = tid; t < len; t += 512) {
        int lab = labb[t];
        ls += xb[(size_t)t * LDIM + lab];
        if (t + 1 < len) ls += trans[lab * LDIM + labb[t + 1]];
    }
    #pragma unroll
    for (int o = 16; o > 0; o >>= 1)
        ls += __shfl_xor_sync(0xffffffffu, ls, o);
    if (l == 0) wred[w] = ls;
    __syncthreads();
    if (tid == 0) {
        float acc = 0.f;
        #pragma unroll
        for (int i = 0; i < 16; i++) acc += wred[i];
        s_labelscore = acc;
    }

    // ------ E rows [32q, 32q+32) of column j: 16 f32x2 registers -------
    unsigned long long E2[16];
    #pragma unroll
    for (int k = 0; k < 16; k++) {
        int i0 = 32 * q + 2 * k;
        float lo = __expf(trans[(i0)     * LDIM + j]);
        float hi = __expf(trans[(i0 + 1) * LDIM + j]);
        E2[k] = pack_f32x2(lo, hi);
    }

    // ---------------- init: U_0j = exp(x_0j - x_00) ---------------------
    float x0 = xb[j];
    if (tid == 0) s_x00 = x0;
    __syncthreads();
    const float x00 = s_x00;
    float Ucur = __expf(x0 - x00);
    if (q == 0) u_sh[0][j + 4 * (j >> 5)] = Ucur;

    // prefetch x two steps ahead
    int i1 = 1 < len ? 1 : 0;
    int i2 = 2 < len ? 2 : (len - 1);
    float xA = xb[(size_t)i1 * LDIM + j];
    float xB = xb[(size_t)i2 * LDIM + j];

    float acc_logr = 0.f;                    // tid 0 only
    const int roff = 36 * q;                 // skewed read base (floats)
    __syncthreads();

    // ---------------- forward recursion: t = 1 .. len-1 ----------------
    int cur = 0;
    for (int t = 1; t < len; t++) {
        const int nxt = cur ^ 1;
        const float u0 = u_sh[cur][0];
        const float r  = rcp_approx(u0);     // off the FFMA chain
        const float ex = __expf(xA);          // off the FFMA chain

        // rotate prefetch (x for t+2)
        xA = xB;
        int tp = t + 2;
        if (tp > len - 1) tp = len - 1;
        xB = xb[(size_t)tp * LDIM + j];

        // partial s: 32 rows = 8 LDS.128 + 16 FFMA2, 4 accumulators
        const ulonglong2* uu = (const ulonglong2*)(u_sh[cur] + roff);
        unsigned long long acc0 = 0ull, acc1 = 0ull, acc2 = 0ull, acc3 = 0ull;
        #pragma unroll
        for (int k = 0; k < 8; k += 4) {
            ulonglong2 ua = uu[k + 0];
            ulonglong2 ub = uu[k + 1];
            ulonglong2 uc = uu[k + 2];
            ulonglong2 ud = uu[k + 3];
            acc0 = fma_f32x2(ua.x, E2[2 * k + 0], acc0);
            acc1 = fma_f32x2(ua.y, E2[2 * k + 1], acc1);
            acc2 = fma_f32x2(ub.x, E2[2 * k + 2], acc2);
            acc3 = fma_f32x2(ub.y, E2[2 * k + 3], acc3);
            acc0 = fma_f32x2(uc.x, E2[2 * k + 4], acc0);
            acc1 = fma_f32x2(uc.y, E2[2 * k + 5], acc1);
            acc2 = fma_f32x2(ud.x, E2[2 * k + 6], acc2);
            acc3 = fma_f32x2(ud.y, E2[2 * k + 7], acc3);
        }
        unsigned long long acc01 = add_f32x2(acc0, acc1);
        unsigned long long acc23 = add_f32x2(acc2, acc3);
        unsigned long long accs  = add_f32x2(acc01, acc23);
        float slo, shi;
        unpack_f32x2(accs, slo, shi);
        float s = slo + shi;

        // combine quarters (bit3 and bit4 of lane = q bits)
        s += __shfl_xor_sync(0xffffffffu, s, 8);
        s += __shfl_xor_sync(0xffffffffu, s, 16);

        Ucur = s * (r * ex);
        if (q == 0) u_sh[nxt][j + 4 * (j >> 5)] = Ucur;
        if (tid == 0) acc_logr += __logf(r);  // offset bookkeeping, off-path
        cur = nxt;
        __syncthreads();
    }

    // ------- z = x00 - acc_logr + log(sum_j U);  out = z - label_score --
    float es = (q == 0) ? Ucur : 0.f;
    #pragma unroll
    for (int o = 16; o > 0; o >>= 1)
        es += __shfl_xor_sync(0xffffffffu, es, o);
    if (l == 0) wred[w] = es;
    __syncthreads();
    if (tid == 0) {
        float ssum = 0.f;
        #pragma unroll
        for (int i = 0; i < 16; i++) ssum += wred[i];
        float z = x00 - acc_logr + logf(ssum);
        out[b] = z - s_labelscore;
    }
}

extern "C" void kernel_launch(void* const* d_in, const int* in_sizes, int n_in,
                              void* d_out, int out_size)
{
    const float* input  = (const float*)d_in[0];   // (B, S, L) f32
    const int*   label  = (const int*)  d_in[1];   // (B, S) i32
    const int*   length = (const int*)  d_in[2];   // (B,) i32
    const float* trans  = (const float*)d_in[3];   // (L, L) f32
    float* out = (float*)d_out;                    // (B, 1) f32

    const int B = in_sizes[2];
    const int S = in_sizes[1] / B;

    sort_len_kernel<<<1, 1024>>>(length, B, S);
    crf_forward_kernel<<<B, 512>>>(input, label, length, trans, out, S);
}